// round 5
// baseline (speedup 1.0000x reference)
#include <cuda_runtime.h>
#include <math.h>
#include <stdint.h>

#define Bsz  64
#define Tlen 2048
#define Hd   128
#define G4   512
#define Cout 7

// ---------------- device scratch ----------------
__device__ float g_v0[G4];                          // W_ih0 @ ff_w
__device__ float g_u0[G4];                          // W_ih0 @ ff_b + b0
__device__ float g_G1[(size_t)Tlen * Bsz * G4];     // layer-1 input-gate preacts [t][b][g]
__device__ float g_pool[Bsz * 3 * Hd];

__device__ __forceinline__ float sigf(float x)  { return 1.0f / (1.0f + __expf(-x)); }
__device__ __forceinline__ float tanhfast(float x) {
    return fmaf(-2.0f, 1.0f / (__expf(2.0f * x) + 1.0f), 1.0f);
}

__device__ __forceinline__ uint32_t smem_u32(const void* p) {
    uint32_t a;
    asm("{ .reg .u64 t; cvta.to.shared.u64 t, %1; cvt.u32.u64 %0, t; }" : "=r"(a) : "l"(p));
    return a;
}
__device__ __forceinline__ uint32_t mapa32(uint32_t a, uint32_t rank) {
    uint32_t d;
    asm("mapa.shared::cluster.u32 %0, %1, %2;" : "=r"(d) : "r"(a), "r"(rank));
    return d;
}
__device__ __forceinline__ void st_async_remote(uint32_t raddr, float v, uint32_t rmbar) {
    asm volatile("st.async.shared::cluster.mbarrier::complete_tx::bytes.b32 [%0], %1, [%2];"
                 :: "r"(raddr), "r"(__float_as_uint(v)), "r"(rmbar) : "memory");
}
__device__ __forceinline__ void mbar_init(uint32_t mbar, uint32_t cnt) {
    asm volatile("mbarrier.init.shared.b64 [%0], %1;" :: "r"(mbar), "r"(cnt) : "memory");
}
__device__ __forceinline__ void mbar_expect_tx(uint32_t mbar, uint32_t bytes) {
    asm volatile("mbarrier.arrive.expect_tx.shared.b64 _, [%0], %1;" :: "r"(mbar), "r"(bytes) : "memory");
}
__device__ __forceinline__ void mbar_wait(uint32_t mbar, uint32_t parity) {
    uint32_t done;
    asm volatile(
        "{\n\t.reg .pred p;\n\t"
        "mbarrier.try_wait.parity.acquire.cluster.shared::cta.b64 p, [%1], %2;\n\t"
        "selp.b32 %0, 1, 0, p;\n\t}"
        : "=r"(done) : "r"(mbar), "r"(parity) : "memory");
    if (!done) {
        asm volatile(
            "{\n\t.reg .pred P1;\n\t"
            "WL_%=:\n\t"
            "mbarrier.try_wait.parity.acquire.cluster.shared::cta.b64 P1, [%0], %1, 0x989680;\n\t"
            "@P1 bra.uni WD_%=;\n\t"
            "bra.uni WL_%=;\n\t"
            "WD_%=:\n\t}"
            :: "r"(mbar), "r"(parity) : "memory");
    }
}

// ---------------- prep (parallelized: 8 CTAs) ----------------
__global__ void prep_kernel(const float* __restrict__ Wih0, const float* __restrict__ ffw,
                            const float* __restrict__ ffb,  const float* __restrict__ b0) {
    int g = blockIdx.x * 64 + threadIdx.x;   // 8 * 64 = 512
    float v = 0.f, u = 0.f;
    #pragma unroll 8
    for (int k = 0; k < Hd; k++) {
        float w = Wih0[g * Hd + k];
        v = fmaf(w, ffw[k], v);
        u = fmaf(w, ffb[k], u);
    }
    g_v0[g] = v;
    g_u0[g] = u + b0[g];
}

// ---------------- cluster-split LSTM layer (64 clusters of 2 CTAs) ----------------
// Thread owns ONE gate g = rank*256 + tid; all 128 W_hh weights in registers.
// LAYER 0 additionally computes the layer-1 input GEMV rows [rank*256, rank*256+256)
// over h(t-1) during the DSMEM act-exchange wait, writing g_G1[t-1] directly
// (the standalone GEMM kernel is eliminated).
template <int LAYER>
__global__ __launch_bounds__(256, 1) __cluster_dims__(2, 1, 1)
void lstm_kernel(const float* __restrict__ Whh,
                 const float* __restrict__ Wih1, const float* __restrict__ b1,
                 const float* __restrict__ xin,
                 const int*   __restrict__ lengths) {
    __shared__ float act[2][G4];
    __shared__ float h_s[Hd];
    __shared__ float xrow[Tlen];
    __shared__ __align__(8) unsigned long long mbar[2];
    extern __shared__ float4 Wg4[];          // LAYER 0: 32*256 float4 = 128 KB, [k4][n]

    const int tid  = threadIdx.x;
    const int rank = blockIdx.x & 1;
    const int b    = blockIdx.x >> 1;
    const int g    = rank * 256 + tid;

    // ---- recurrent weights fully in registers ----
    float4 w[32];
    #pragma unroll
    for (int j = 0; j < 32; j++)
        w[j] = *(const float4*)(Whh + (size_t)g * Hd + 4 * j);

    // ---- mbarriers ----
    uint32_t mb0 = smem_u32(&mbar[0]);
    uint32_t mb1 = smem_u32(&mbar[1]);
    if (tid == 0) {
        mbar_init(mb0, 1); mbar_init(mb1, 1);
        mbar_expect_tx(mb0, 1024); mbar_expect_tx(mb1, 1024);
    }
    const uint32_t peer = rank ^ 1;
    const uint32_t r_act0 = mapa32(smem_u32(&act[0][g]), peer);
    const uint32_t r_act1 = mapa32(smem_u32(&act[1][g]), peer);
    const uint32_t r_mb0  = mapa32(mb0, peer);
    const uint32_t r_mb1  = mapa32(mb1, peer);

    float vg = 0.f, ug = 0.f, bz = 0.f;
    if (LAYER == 0) {
        vg = g_v0[g]; ug = g_u0[g];
        for (int i = tid; i < Tlen; i += 256) xrow[i] = xin[(size_t)b * Tlen + i];
        // stage GEMV weights transposed [k4][n]: rows [rank*256, +256) of Wih1
        for (int i = tid; i < 256 * 32; i += 256) {
            int n = i & 255, k4 = i >> 8;
            Wg4[k4 * 256 + n] = *(const float4*)(Wih1 + (size_t)(rank * 256 + n) * Hd + 4 * k4);
        }
        bz = b1[g];
    }
    if (tid < Hd) h_s[tid] = 0.f;
    __syncthreads();
    asm volatile("barrier.cluster.arrive.aligned;" ::: "memory");
    asm volatile("barrier.cluster.wait.aligned;" ::: "memory");

    float cst = 0.f, sum = 0.f, mx = -INFINITY, last = 0.f;
    const int len = lengths[b];
    uint32_t ph0 = 0, ph1 = 0;

    float zn = 0.f;
    if (LAYER == 1) zn = g_G1[(size_t)b * G4 + g];   // prefetch t=0

    const float4* h4 = (const float4*)h_s;

    for (int t = 0; t < Tlen; t++) {
        const int p = t & 1;

        float a0, a1 = 0.f;
        if (LAYER == 0) {
            a0 = fmaf(xrow[t], vg, ug);
        } else {
            a0 = zn;
            if (t + 1 < Tlen) zn = g_G1[((size_t)(t + 1) * Bsz + b) * G4 + g];
        }
        #pragma unroll
        for (int j = 0; j < 32; j++) {
            float4 hv = h4[j], wv = w[j];
            a0 = fmaf(hv.x, wv.x, a0);
            a1 = fmaf(hv.y, wv.y, a1);
            a0 = fmaf(hv.z, wv.z, a0);
            a1 = fmaf(hv.w, wv.w, a1);
        }
        float A = a0 + a1;

        float av;
        if (rank == 0)           av = sigf(A);       // i, f
        else if (tid < 128)      av = tanhfast(A);   // g
        else                     av = sigf(A);       // o

        // launch DSMEM flight first, then overlap it with the GEMV
        st_async_remote(p ? r_act1 : r_act0, av, p ? r_mb1 : r_mb0);
        act[p][g] = av;

        if (LAYER == 0 && t > 0) {
            // z(t-1) = Wih1[g,:] . h(t-1)  (h_s still holds h(t-1))
            float z = bz;
            #pragma unroll
            for (int k4 = 0; k4 < 32; k4++) {
                float4 wv = Wg4[k4 * 256 + tid], hv = h4[k4];
                z = fmaf(hv.x, wv.x, z);
                z = fmaf(hv.y, wv.y, z);
                z = fmaf(hv.z, wv.z, z);
                z = fmaf(hv.w, wv.w, z);
            }
            g_G1[((size_t)(t - 1) * Bsz + b) * G4 + g] = z;
        }
        __syncthreads();   // local act half visible

        if (tid < Hd) {
            if (p == 0) { mbar_wait(mb0, ph0); } else { mbar_wait(mb1, ph1); }
            if (tid == 0) mbar_expect_tx(p ? mb1 : mb0, 1024);
            float iv = act[p][tid],          fv = act[p][Hd + tid];
            float gv = act[p][2 * Hd + tid], ov = act[p][3 * Hd + tid];
            cst = fmaf(fv, cst, iv * gv);
            float h = ov * tanhfast(cst);
            h_s[tid] = h;
            if (LAYER == 1 && rank == 0) {
                if (t < len) { sum += h; mx = fmaxf(mx, h); }
                if (t == len - 1) last = h;
            }
        }
        if (p == 0) ph0 ^= 1; else ph1 ^= 1;
        __syncthreads();
    }

    if (LAYER == 0) {
        // epilogue GEMV for h(2047)
        float z = bz;
        #pragma unroll
        for (int k4 = 0; k4 < 32; k4++) {
            float4 wv = Wg4[k4 * 256 + tid], hv = h4[k4];
            z = fmaf(hv.x, wv.x, z);
            z = fmaf(hv.y, wv.y, z);
            z = fmaf(hv.z, wv.z, z);
            z = fmaf(hv.w, wv.w, z);
        }
        g_G1[((size_t)(Tlen - 1) * Bsz + b) * G4 + g] = z;
    }

    if (LAYER == 1 && rank == 0 && tid < Hd) {
        g_pool[b * 384 + tid]          = sum / (float)len;
        g_pool[b * 384 + Hd + tid]     = mx;
        g_pool[b * 384 + 2 * Hd + tid] = last;
    }
    asm volatile("barrier.cluster.arrive.aligned;" ::: "memory");
    asm volatile("barrier.cluster.wait.aligned;" ::: "memory");
}

// ---------------- final linear ----------------
__global__ void final_kernel(const float* __restrict__ lw, const float* __restrict__ lb,
                             float* __restrict__ out) {
    int tid = blockIdx.x * blockDim.x + threadIdx.x;
    if (tid >= Bsz * Cout) return;
    int b = tid / Cout, c = tid % Cout;
    float s = lb[c];
    const float* p = g_pool + b * 384;
    const float* w = lw + c * 384;
    #pragma unroll 8
    for (int j = 0; j < 384; j++) s = fmaf(p[j], w[j], s);
    out[tid] = s;
}

// ---------------- launch ----------------
extern "C" void kernel_launch(void* const* d_in, const int* in_sizes, int n_in,
                              void* d_out, int out_size) {
    const float* x    = (const float*)d_in[0];
    const int*   lens = (const int*)  d_in[1];
    const float* ffw  = (const float*)d_in[2];
    const float* ffb  = (const float*)d_in[3];
    const float* Wih0 = (const float*)d_in[4];
    const float* Whh0 = (const float*)d_in[5];
    const float* b0   = (const float*)d_in[6];
    const float* Wih1 = (const float*)d_in[7];
    const float* Whh1 = (const float*)d_in[8];
    const float* b1   = (const float*)d_in[9];
    const float* lw   = (const float*)d_in[10];
    const float* lb   = (const float*)d_in[11];
    float* out = (float*)d_out;

    const int GEMV_SMEM = 32 * 256 * 16;   // 128 KB dynamic for Wg4
    cudaFuncSetAttribute(lstm_kernel<0>, cudaFuncAttributeMaxDynamicSharedMemorySize, GEMV_SMEM);

    prep_kernel<<<8, 64>>>(Wih0, ffw, ffb, b0);
    lstm_kernel<0><<<2 * Bsz, 256, GEMV_SMEM>>>(Whh0, Wih1, b1, x, lens);
    lstm_kernel<1><<<2 * Bsz, 256, 0>>>(Whh1, Wih1, b1, x, lens);
    final_kernel<<<1, 512>>>(lw, lb, out);
}

// round 6
// speedup vs baseline: 1.2674x; 1.2674x over previous
#include <cuda_runtime.h>
#include <math.h>
#include <stdint.h>

#define Bsz  64
#define Tlen 2048
#define Hd   128
#define G4   512
#define Cout 7
#define CHUNK 8

// ---------------- device scratch ----------------
__device__ float g_v0[G4];
__device__ float g_u0[G4];
__device__ float g_G1[(size_t)Tlen * Bsz * G4];     // layer-1 input-gate preacts [t][b][g]
__device__ float g_pool[Bsz * 3 * Hd];

__device__ __forceinline__ float sigf(float x)  { return 1.0f / (1.0f + __expf(-x)); }
__device__ __forceinline__ float tanhfast(float x) {
    return fmaf(-2.0f, 1.0f / (__expf(2.0f * x) + 1.0f), 1.0f);
}

__device__ __forceinline__ uint32_t smem_u32(const void* p) {
    uint32_t a;
    asm("{ .reg .u64 t; cvta.to.shared.u64 t, %1; cvt.u32.u64 %0, t; }" : "=r"(a) : "l"(p));
    return a;
}
__device__ __forceinline__ uint32_t mapa32(uint32_t a, uint32_t rank) {
    uint32_t d;
    asm("mapa.shared::cluster.u32 %0, %1, %2;" : "=r"(d) : "r"(a), "r"(rank));
    return d;
}
__device__ __forceinline__ void st_async_remote(uint32_t raddr, float v, uint32_t rmbar) {
    asm volatile("st.async.shared::cluster.mbarrier::complete_tx::bytes.b32 [%0], %1, [%2];"
                 :: "r"(raddr), "r"(__float_as_uint(v)), "r"(rmbar) : "memory");
}
__device__ __forceinline__ void mbar_init(uint32_t mbar, uint32_t cnt) {
    asm volatile("mbarrier.init.shared.b64 [%0], %1;" :: "r"(mbar), "r"(cnt) : "memory");
}
__device__ __forceinline__ void mbar_expect_tx(uint32_t mbar, uint32_t bytes) {
    asm volatile("mbarrier.arrive.expect_tx.shared.b64 _, [%0], %1;" :: "r"(mbar), "r"(bytes) : "memory");
}
__device__ __forceinline__ void mbar_wait(uint32_t mbar, uint32_t parity) {
    uint32_t done;
    asm volatile(
        "{\n\t.reg .pred p;\n\t"
        "mbarrier.try_wait.parity.acquire.cluster.shared::cta.b64 p, [%1], %2;\n\t"
        "selp.b32 %0, 1, 0, p;\n\t}"
        : "=r"(done) : "r"(mbar), "r"(parity) : "memory");
    if (!done) {
        asm volatile(
            "{\n\t.reg .pred P1;\n\t"
            "WL_%=:\n\t"
            "mbarrier.try_wait.parity.acquire.cluster.shared::cta.b64 P1, [%0], %1, 0x989680;\n\t"
            "@P1 bra.uni WD_%=;\n\t"
            "bra.uni WL_%=;\n\t"
            "WD_%=:\n\t}"
            :: "r"(mbar), "r"(parity) : "memory");
    }
}

// ---------------- prep ----------------
__global__ void prep_kernel(const float* __restrict__ Wih0, const float* __restrict__ ffw,
                            const float* __restrict__ ffb,  const float* __restrict__ b0) {
    int g = blockIdx.x * 64 + threadIdx.x;   // 8 * 64
    float v = 0.f, u = 0.f;
    #pragma unroll 8
    for (int k = 0; k < Hd; k++) {
        float w = Wih0[g * Hd + k];
        v = fmaf(w, ffw[k], v);
        u = fmaf(w, ffb[k], u);
    }
    g_v0[g] = v;
    g_u0[g] = u + b0[g];
}

// ---------------- cluster-split LSTM layer (64 clusters of 2 CTAs) ----------------
// Thread owns ONE gate g = rank*256 + tid; all 128 W_hh weights in registers.
// LAYER 0: h(t) buffered into an 8-step smem ring; every 8 steps a chunk-GEMV
// computes G1[t-7..t] with each Wih1 float4 loaded ONCE per chunk (weight
// traffic amortized 8x -- the fix for the R5 crossbar blowup).
template <int LAYER>
__global__ __launch_bounds__(256, 1) __cluster_dims__(2, 1, 1)
void lstm_kernel(const float* __restrict__ Whh,
                 const float* __restrict__ Wih1, const float* __restrict__ b1,
                 const float* __restrict__ xin,
                 const int*   __restrict__ lengths) {
    __shared__ float act[2][G4];
    __shared__ float h_s[Hd];
    __shared__ float xrow[Tlen];
    __shared__ float4 hbuf4[CHUNK][Hd / 4];          // 4 KB h ring (LAYER 0)
    __shared__ __align__(8) unsigned long long mbar[2];
    extern __shared__ float4 Wg4[];                  // LAYER 0: 32*256 float4 = 128 KB, [k4][n]

    const int tid  = threadIdx.x;
    const int rank = blockIdx.x & 1;
    const int b    = blockIdx.x >> 1;
    const int g    = rank * 256 + tid;

    // ---- recurrent weights fully in registers ----
    float4 w[32];
    #pragma unroll
    for (int j = 0; j < 32; j++)
        w[j] = *(const float4*)(Whh + (size_t)g * Hd + 4 * j);

    // ---- mbarriers ----
    uint32_t mb0 = smem_u32(&mbar[0]);
    uint32_t mb1 = smem_u32(&mbar[1]);
    if (tid == 0) {
        mbar_init(mb0, 1); mbar_init(mb1, 1);
        mbar_expect_tx(mb0, 1024); mbar_expect_tx(mb1, 1024);
    }
    const uint32_t peer = rank ^ 1;
    const uint32_t r_act0 = mapa32(smem_u32(&act[0][g]), peer);
    const uint32_t r_act1 = mapa32(smem_u32(&act[1][g]), peer);
    const uint32_t r_mb0  = mapa32(mb0, peer);
    const uint32_t r_mb1  = mapa32(mb1, peer);

    float vg = 0.f, ug = 0.f, bz = 0.f;
    if (LAYER == 0) {
        vg = g_v0[g]; ug = g_u0[g];
        for (int i = tid; i < Tlen; i += 256) xrow[i] = xin[(size_t)b * Tlen + i];
        for (int i = tid; i < 256 * 32; i += 256) {
            int n = i & 255, k4 = i >> 8;
            Wg4[k4 * 256 + n] = *(const float4*)(Wih1 + (size_t)(rank * 256 + n) * Hd + 4 * k4);
        }
        bz = b1[g];
    }
    if (tid < Hd) h_s[tid] = 0.f;
    __syncthreads();
    asm volatile("barrier.cluster.arrive.aligned;" ::: "memory");
    asm volatile("barrier.cluster.wait.aligned;" ::: "memory");

    float cst = 0.f, sum = 0.f, mx = -INFINITY, last = 0.f;
    const int len = lengths[b];
    uint32_t ph0 = 0, ph1 = 0;

    float zn = 0.f;
    if (LAYER == 1) zn = g_G1[(size_t)b * G4 + g];   // prefetch t=0

    const float4* h4 = (const float4*)h_s;

    for (int t = 0; t < Tlen; t++) {
        const int p = t & 1;

        float a0, a1 = 0.f;
        if (LAYER == 0) {
            a0 = fmaf(xrow[t], vg, ug);
        } else {
            a0 = zn;
            if (t + 1 < Tlen) zn = g_G1[((size_t)(t + 1) * Bsz + b) * G4 + g];
        }
        #pragma unroll
        for (int j = 0; j < 32; j++) {
            float4 hv = h4[j], wv = w[j];
            a0 = fmaf(hv.x, wv.x, a0);
            a1 = fmaf(hv.y, wv.y, a1);
            a0 = fmaf(hv.z, wv.z, a0);
            a1 = fmaf(hv.w, wv.w, a1);
        }
        float A = a0 + a1;

        float av;
        if (rank == 0)           av = sigf(A);       // i, f
        else if (tid < 128)      av = tanhfast(A);   // g
        else                     av = sigf(A);       // o

        st_async_remote(p ? r_act1 : r_act0, av, p ? r_mb1 : r_mb0);
        act[p][g] = av;
        __syncthreads();   // local act half visible

        if (tid < Hd) {
            if (p == 0) { mbar_wait(mb0, ph0); } else { mbar_wait(mb1, ph1); }
            if (tid == 0) mbar_expect_tx(p ? mb1 : mb0, 1024);
            float iv = act[p][tid],          fv = act[p][Hd + tid];
            float gv = act[p][2 * Hd + tid], ov = act[p][3 * Hd + tid];
            cst = fmaf(fv, cst, iv * gv);
            float h = ov * tanhfast(cst);
            h_s[tid] = h;
            if (LAYER == 0) {
                ((float*)hbuf4[t & (CHUNK - 1)])[tid] = h;
            } else if (rank == 0) {
                if (t < len) { sum += h; mx = fmaxf(mx, h); }
                if (t == len - 1) last = h;
            }
        }
        if (p == 0) ph0 ^= 1; else ph1 ^= 1;
        __syncthreads();

        // ---- chunk GEMV: every 8 steps, weights read once, 8 h's from ring ----
        // Safe: hbuf slot 0 is next overwritten only after step t+1's act-barrier,
        // which no thread reaches before finishing this gemv.
        if (LAYER == 0 && (t & (CHUNK - 1)) == (CHUNK - 1)) {
            float z[CHUNK];
            #pragma unroll
            for (int tt = 0; tt < CHUNK; tt++) z[tt] = bz;
            #pragma unroll
            for (int k4 = 0; k4 < 32; k4++) {
                float4 wv = Wg4[k4 * 256 + tid];
                #pragma unroll
                for (int tt = 0; tt < CHUNK; tt++) {
                    float4 hv = hbuf4[tt][k4];
                    z[tt] = fmaf(hv.x, wv.x, z[tt]);
                    z[tt] = fmaf(hv.y, wv.y, z[tt]);
                    z[tt] = fmaf(hv.z, wv.z, z[tt]);
                    z[tt] = fmaf(hv.w, wv.w, z[tt]);
                }
            }
            const int tb = t - (CHUNK - 1);
            #pragma unroll
            for (int tt = 0; tt < CHUNK; tt++)
                g_G1[((size_t)(tb + tt) * Bsz + b) * G4 + g] = z[tt];
        }
    }

    if (LAYER == 1 && rank == 0 && tid < Hd) {
        g_pool[b * 384 + tid]          = sum / (float)len;
        g_pool[b * 384 + Hd + tid]     = mx;
        g_pool[b * 384 + 2 * Hd + tid] = last;
    }
    asm volatile("barrier.cluster.arrive.aligned;" ::: "memory");
    asm volatile("barrier.cluster.wait.aligned;" ::: "memory");
}

// ---------------- final linear: 64 CTAs, warp w computes class c=w ----------------
__global__ __launch_bounds__(256)
void final_kernel(const float* __restrict__ lw, const float* __restrict__ lb,
                  float* __restrict__ out) {
    const int b = blockIdx.x;
    const int wid = threadIdx.x >> 5;   // 0..7 (warp 7 idle)
    const int lane = threadIdx.x & 31;
    if (wid >= Cout) return;
    float s = 0.f;
    const float* p = g_pool + b * 384;
    const float* wv = lw + wid * 384;
    #pragma unroll
    for (int j = lane; j < 384; j += 32) s = fmaf(p[j], wv[j], s);
    #pragma unroll
    for (int o = 16; o > 0; o >>= 1) s += __shfl_xor_sync(0xffffffff, s, o);
    if (lane == 0) out[b * Cout + wid] = s + lb[wid];
}

// ---------------- launch ----------------
extern "C" void kernel_launch(void* const* d_in, const int* in_sizes, int n_in,
                              void* d_out, int out_size) {
    const float* x    = (const float*)d_in[0];
    const int*   lens = (const int*)  d_in[1];
    const float* ffw  = (const float*)d_in[2];
    const float* ffb  = (const float*)d_in[3];
    const float* Wih0 = (const float*)d_in[4];
    const float* Whh0 = (const float*)d_in[5];
    const float* b0   = (const float*)d_in[6];
    const float* Wih1 = (const float*)d_in[7];
    const float* Whh1 = (const float*)d_in[8];
    const float* b1   = (const float*)d_in[9];
    const float* lw   = (const float*)d_in[10];
    const float* lb   = (const float*)d_in[11];
    float* out = (float*)d_out;

    const int GEMV_SMEM = 32 * 256 * 16;   // 128 KB dynamic for Wg4
    cudaFuncSetAttribute(lstm_kernel<0>, cudaFuncAttributeMaxDynamicSharedMemorySize, GEMV_SMEM);

    prep_kernel<<<8, 64>>>(Wih0, ffw, ffb, b0);
    lstm_kernel<0><<<2 * Bsz, 256, GEMV_SMEM>>>(Whh0, Wih1, b1, x, lens);
    lstm_kernel<1><<<2 * Bsz, 256, 0>>>(Whh1, Wih1, b1, x, lens);
    final_kernel<<<Bsz, 256>>>(lw, lb, out);
}

// round 7
// speedup vs baseline: 1.2868x; 1.0153x over previous
#include <cuda_runtime.h>
#include <math.h>
#include <stdint.h>

#define Bsz  64
#define Tlen 2048
#define Hd   128
#define G4   512
#define Cout 7
#define CHUNK 8

// ---------------- device scratch ----------------
__device__ float g_v0[G4];
__device__ float g_u0[G4];
__device__ float g_G1[(size_t)Tlen * Bsz * G4];     // layer-1 input-gate preacts [t][b][g]
__device__ float g_pool[Bsz * 3 * Hd];

__device__ __forceinline__ float sigf(float x)  { return 1.0f / (1.0f + __expf(-x)); }
__device__ __forceinline__ float tanhfast(float x) {
    return fmaf(-2.0f, 1.0f / (__expf(2.0f * x) + 1.0f), 1.0f);
}

// ---- packed f32x2 (Blackwell FFMA2; ptxas never auto-fuses) ----
__device__ __forceinline__ void fma2(unsigned long long& d, unsigned long long a, unsigned long long b) {
    asm("fma.rn.f32x2 %0, %1, %2, %0;" : "+l"(d) : "l"(a), "l"(b));
}
__device__ __forceinline__ float2 upk2(unsigned long long v) {
    float2 r; asm("mov.b64 {%0, %1}, %2;" : "=f"(r.x), "=f"(r.y) : "l"(v)); return r;
}

__device__ __forceinline__ uint32_t smem_u32(const void* p) {
    uint32_t a;
    asm("{ .reg .u64 t; cvta.to.shared.u64 t, %1; cvt.u32.u64 %0, t; }" : "=r"(a) : "l"(p));
    return a;
}
__device__ __forceinline__ uint32_t mapa32(uint32_t a, uint32_t rank) {
    uint32_t d;
    asm("mapa.shared::cluster.u32 %0, %1, %2;" : "=r"(d) : "r"(a), "r"(rank));
    return d;
}
__device__ __forceinline__ void st_async_remote(uint32_t raddr, float v, uint32_t rmbar) {
    asm volatile("st.async.shared::cluster.mbarrier::complete_tx::bytes.b32 [%0], %1, [%2];"
                 :: "r"(raddr), "r"(__float_as_uint(v)), "r"(rmbar) : "memory");
}
__device__ __forceinline__ void mbar_init(uint32_t mbar, uint32_t cnt) {
    asm volatile("mbarrier.init.shared.b64 [%0], %1;" :: "r"(mbar), "r"(cnt) : "memory");
}
__device__ __forceinline__ void mbar_expect_tx(uint32_t mbar, uint32_t bytes) {
    asm volatile("mbarrier.arrive.expect_tx.shared.b64 _, [%0], %1;" :: "r"(mbar), "r"(bytes) : "memory");
}
__device__ __forceinline__ void mbar_wait(uint32_t mbar, uint32_t parity) {
    uint32_t done;
    asm volatile(
        "{\n\t.reg .pred p;\n\t"
        "mbarrier.try_wait.parity.acquire.cluster.shared::cta.b64 p, [%1], %2;\n\t"
        "selp.b32 %0, 1, 0, p;\n\t}"
        : "=r"(done) : "r"(mbar), "r"(parity) : "memory");
    if (!done) {
        asm volatile(
            "{\n\t.reg .pred P1;\n\t"
            "WL_%=:\n\t"
            "mbarrier.try_wait.parity.acquire.cluster.shared::cta.b64 P1, [%0], %1, 0x989680;\n\t"
            "@P1 bra.uni WD_%=;\n\t"
            "bra.uni WL_%=;\n\t"
            "WD_%=:\n\t}"
            :: "r"(mbar), "r"(parity) : "memory");
    }
}

// ---------------- prep ----------------
__global__ void prep_kernel(const float* __restrict__ Wih0, const float* __restrict__ ffw,
                            const float* __restrict__ ffb,  const float* __restrict__ b0) {
    int g = blockIdx.x * 64 + threadIdx.x;   // 8 * 64
    float v = 0.f, u = 0.f;
    #pragma unroll 8
    for (int k = 0; k < Hd; k++) {
        float w = Wih0[g * Hd + k];
        v = fmaf(w, ffw[k], v);
        u = fmaf(w, ffb[k], u);
    }
    g_v0[g] = v;
    g_u0[g] = u + b0[g];
}

// ---------------- cluster-split LSTM layer (64 clusters of 2 CTAs) ----------------
// Thread owns ONE gate g = rank*256 + tid; 128 W_hh weights packed f32x2 in regs.
// Matvec runs on FFMA2 (half the issue slots of scalar FFMA).
// LAYER 0: layer-1 input GEMV spread 1/8-per-step over the PREVIOUS 8-step chunk
// (16-slot h ring), scheduled right after st.async so it fills the DSMEM flight.
template <int LAYER>
__global__ __launch_bounds__(256, 1) __cluster_dims__(2, 1, 1)
void lstm_kernel(const float* __restrict__ Whh,
                 const float* __restrict__ Wih1, const float* __restrict__ b1,
                 const float* __restrict__ xin,
                 const int*   __restrict__ lengths) {
    __shared__ float act[2][G4];
    __shared__ __align__(16) float h_s[Hd];
    __shared__ float xrow[Tlen];
    __shared__ __align__(16) float hring[2 * CHUNK][Hd];   // 8 KB (LAYER 0)
    __shared__ __align__(8) unsigned long long mbar[2];
    extern __shared__ __align__(16) float Wg[];            // LAYER 0: [k4][n] float4, 128 KB

    const int tid  = threadIdx.x;
    const int rank = blockIdx.x & 1;
    const int b    = blockIdx.x >> 1;
    const int g    = rank * 256 + tid;

    // ---- recurrent weights: 32 x ulonglong2 = 64 packed f32x2 pairs ----
    ulonglong2 w2[32];
    #pragma unroll
    for (int j = 0; j < 32; j++)
        w2[j] = *(const ulonglong2*)(Whh + (size_t)g * Hd + 4 * j);

    // ---- mbarriers ----
    uint32_t mb0 = smem_u32(&mbar[0]);
    uint32_t mb1 = smem_u32(&mbar[1]);
    if (tid == 0) {
        mbar_init(mb0, 1); mbar_init(mb1, 1);
        mbar_expect_tx(mb0, 1024); mbar_expect_tx(mb1, 1024);
    }
    const uint32_t peer = rank ^ 1;
    const uint32_t r_act0 = mapa32(smem_u32(&act[0][g]), peer);
    const uint32_t r_act1 = mapa32(smem_u32(&act[1][g]), peer);
    const uint32_t r_mb0  = mapa32(mb0, peer);
    const uint32_t r_mb1  = mapa32(mb1, peer);

    float vg = 0.f, ug = 0.f, bz = 0.f;
    if (LAYER == 0) {
        vg = g_v0[g]; ug = g_u0[g];
        for (int i = tid; i < Tlen; i += 256) xrow[i] = xin[(size_t)b * Tlen + i];
        // GEMV weights transposed [k4][n]: rows [rank*256, +256) of Wih1
        for (int i = tid; i < 256 * 32; i += 256) {
            int n = i & 255, k4 = i >> 8;
            ((float4*)Wg)[k4 * 256 + n] = *(const float4*)(Wih1 + (size_t)(rank * 256 + n) * Hd + 4 * k4);
        }
        bz = b1[g];
    }
    if (tid < Hd) h_s[tid] = 0.f;
    __syncthreads();
    asm volatile("barrier.cluster.arrive.aligned;" ::: "memory");
    asm volatile("barrier.cluster.wait.aligned;" ::: "memory");

    float cst = 0.f, sum = 0.f, mx = -INFINITY, last = 0.f;
    const int len = lengths[b];
    uint32_t ph0 = 0, ph1 = 0;

    float zn = 0.f;
    if (LAYER == 1) zn = g_G1[(size_t)b * G4 + g];   // prefetch t=0

    const ulonglong2* h2v = (const ulonglong2*)h_s;
    const ulonglong2* Wg2 = (const ulonglong2*)Wg;
    unsigned long long zacc[CHUNK];
    #pragma unroll
    for (int tt = 0; tt < CHUNK; tt++) zacc[tt] = 0ULL;

    for (int t = 0; t < Tlen; t++) {
        const int p = t & 1;

        // ---- recurrent matvec on FFMA2 ----
        float a_in;
        if (LAYER == 0) {
            a_in = fmaf(xrow[t], vg, ug);
        } else {
            a_in = zn;
            if (t + 1 < Tlen) zn = g_G1[((size_t)(t + 1) * Bsz + b) * G4 + g];
        }
        unsigned long long acc0 = 0ULL, acc1 = 0ULL;
        #pragma unroll
        for (int j = 0; j < 32; j++) {
            ulonglong2 hv = h2v[j];
            fma2(acc0, hv.x, w2[j].x);
            fma2(acc1, hv.y, w2[j].y);
        }
        float2 u0 = upk2(acc0), u1 = upk2(acc1);
        float A = a_in + ((u0.x + u0.y) + (u1.x + u1.y));

        float av;
        if (rank == 0)           av = sigf(A);       // i, f
        else if (tid < 128)      av = tanhfast(A);   // g
        else                     av = sigf(A);       // o

        // launch the DSMEM flight, then fill it with spread GEMV work
        st_async_remote(p ? r_act1 : r_act0, av, p ? r_mb1 : r_mb0);
        act[p][g] = av;

        if (LAYER == 0 && t >= CHUNK) {
            // 1/8 of previous chunk's GEMV: k-pairs [8s, 8s+8) over 8 buffered h's
            const int s = t & (CHUNK - 1);
            const int pc = (t >> 3) - 1;                       // previous chunk id
            const float* hb = hring[(pc & 1) * CHUNK];
            #pragma unroll
            for (int q = 0; q < 4; q++) {
                ulonglong2 wv = Wg2[(4 * s + q) * 256 + tid];
                #pragma unroll
                for (int tt = 0; tt < CHUNK; tt++) {
                    ulonglong2 hv = ((const ulonglong2*)(hb + tt * Hd))[4 * s + q];
                    fma2(zacc[tt], hv.x, wv.x);
                    fma2(zacc[tt], hv.y, wv.y);
                }
            }
            if (s == CHUNK - 1) {                              // chunk done: store + reset
                const int tb = pc * CHUNK;
                #pragma unroll
                for (int tt = 0; tt < CHUNK; tt++) {
                    float2 z2 = upk2(zacc[tt]);
                    g_G1[((size_t)(tb + tt) * Bsz + b) * G4 + g] = bz + z2.x + z2.y;
                    zacc[tt] = 0ULL;
                }
            }
        }
        __syncthreads();   // local act half visible (and gemv done before h overwrite)

        if (tid < Hd) {
            if (p == 0) { mbar_wait(mb0, ph0); } else { mbar_wait(mb1, ph1); }
            if (tid == 0) mbar_expect_tx(p ? mb1 : mb0, 1024);
            float iv = act[p][tid],          fv = act[p][Hd + tid];
            float gv = act[p][2 * Hd + tid], ov = act[p][3 * Hd + tid];
            cst = fmaf(fv, cst, iv * gv);
            float h = ov * tanhfast(cst);
            h_s[tid] = h;
            if (LAYER == 0) {
                hring[t & (2 * CHUNK - 1)][tid] = h;
            } else if (rank == 0) {
                if (t < len) { sum += h; mx = fmaxf(mx, h); }
                if (t == len - 1) last = h;
            }
        }
        if (p == 0) ph0 ^= 1; else ph1 ^= 1;
        __syncthreads();
    }

    if (LAYER == 0) {
        // epilogue: GEMV for the final chunk (t = 2040..2047, ring slots 8..15)
        const int pc = (Tlen >> 3) - 1;
        const float* hb = hring[(pc & 1) * CHUNK];
        #pragma unroll
        for (int tt = 0; tt < CHUNK; tt++) zacc[tt] = 0ULL;
        #pragma unroll 8
        for (int q4 = 0; q4 < 32; q4++) {
            ulonglong2 wv = Wg2[q4 * 256 + tid];
            #pragma unroll
            for (int tt = 0; tt < CHUNK; tt++) {
                ulonglong2 hv = ((const ulonglong2*)(hb + tt * Hd))[q4];
                fma2(zacc[tt], hv.x, wv.x);
                fma2(zacc[tt], hv.y, wv.y);
            }
        }
        const int tb = pc * CHUNK;
        #pragma unroll
        for (int tt = 0; tt < CHUNK; tt++) {
            float2 z2 = upk2(zacc[tt]);
            g_G1[((size_t)(tb + tt) * Bsz + b) * G4 + g] = bz + z2.x + z2.y;
        }
    }

    if (LAYER == 1 && rank == 0 && tid < Hd) {
        g_pool[b * 384 + tid]          = sum / (float)len;
        g_pool[b * 384 + Hd + tid]     = mx;
        g_pool[b * 384 + 2 * Hd + tid] = last;
    }
    asm volatile("barrier.cluster.arrive.aligned;" ::: "memory");
    asm volatile("barrier.cluster.wait.aligned;" ::: "memory");
}

// ---------------- final linear: 64 CTAs, warp w -> class w ----------------
__global__ __launch_bounds__(256)
void final_kernel(const float* __restrict__ lw, const float* __restrict__ lb,
                  float* __restrict__ out) {
    const int b = blockIdx.x;
    const int wid = threadIdx.x >> 5;
    const int lane = threadIdx.x & 31;
    if (wid >= Cout) return;
    float s = 0.f;
    const float* p = g_pool + b * 384;
    const float* wv = lw + wid * 384;
    #pragma unroll
    for (int j = lane; j < 384; j += 32) s = fmaf(p[j], wv[j], s);
    #pragma unroll
    for (int o = 16; o > 0; o >>= 1) s += __shfl_xor_sync(0xffffffff, s, o);
    if (lane == 0) out[b * Cout + wid] = s + lb[wid];
}

// ---------------- launch ----------------
extern "C" void kernel_launch(void* const* d_in, const int* in_sizes, int n_in,
                              void* d_out, int out_size) {
    const float* x    = (const float*)d_in[0];
    const int*   lens = (const int*)  d_in[1];
    const float* ffw  = (const float*)d_in[2];
    const float* ffb  = (const float*)d_in[3];
    const float* Wih0 = (const float*)d_in[4];
    const float* Whh0 = (const float*)d_in[5];
    const float* b0   = (const float*)d_in[6];
    const float* Wih1 = (const float*)d_in[7];
    const float* Whh1 = (const float*)d_in[8];
    const float* b1   = (const float*)d_in[9];
    const float* lw   = (const float*)d_in[10];
    const float* lb   = (const float*)d_in[11];
    float* out = (float*)d_out;

    const int GEMV_SMEM = 32 * 256 * 16;   // 128 KB dynamic for Wg
    cudaFuncSetAttribute(lstm_kernel<0>, cudaFuncAttributeMaxDynamicSharedMemorySize, GEMV_SMEM);

    prep_kernel<<<8, 64>>>(Wih0, ffw, ffb, b0);
    lstm_kernel<0><<<2 * Bsz, 256, GEMV_SMEM>>>(Whh0, Wih1, b1, x, lens);
    lstm_kernel<1><<<2 * Bsz, 256, 0>>>(Whh1, Wih1, b1, x, lens);
    final_kernel<<<Bsz, 256>>>(lw, lb, out);
}

// round 8
// speedup vs baseline: 1.3626x; 1.0589x over previous
#include <cuda_runtime.h>
#include <math.h>
#include <stdint.h>

#define Bsz  64
#define Tlen 2048
#define Hd   128
#define G4   512
#define Cout 7

// ---------------- device scratch ----------------
__device__ float g_v0[G4];
__device__ float g_u0[G4];
__device__ float g_H1[(size_t)Tlen * Bsz * Hd];     // layer-0 h stream [t][b][h]
__device__ float g_G1[(size_t)Tlen * Bsz * G4];     // layer-1 input-gate preacts [t][b][g]
__device__ float g_pool[Bsz * 3 * Hd];

__device__ __forceinline__ float sigf(float x)  { return 1.0f / (1.0f + __expf(-x)); }
__device__ __forceinline__ float tanhfast(float x) {
    return fmaf(-2.0f, 1.0f / (__expf(2.0f * x) + 1.0f), 1.0f);
}

// ---- packed f32x2 (Blackwell FFMA2; ptxas never auto-fuses) ----
__device__ __forceinline__ void fma2(unsigned long long& d, unsigned long long a, unsigned long long b) {
    asm("fma.rn.f32x2 %0, %1, %2, %0;" : "+l"(d) : "l"(a), "l"(b));
}
__device__ __forceinline__ float2 upk2(unsigned long long v) {
    float2 r; asm("mov.b64 {%0, %1}, %2;" : "=f"(r.x), "=f"(r.y) : "l"(v)); return r;
}
__device__ __forceinline__ unsigned long long splat2(float f) {
    unsigned long long v; asm("mov.b64 %0, {%1, %1};" : "=l"(v) : "f"(f)); return v;
}

__device__ __forceinline__ uint32_t smem_u32(const void* p) {
    uint32_t a;
    asm("{ .reg .u64 t; cvta.to.shared.u64 t, %1; cvt.u32.u64 %0, t; }" : "=r"(a) : "l"(p));
    return a;
}
__device__ __forceinline__ uint32_t mapa32(uint32_t a, uint32_t rank) {
    uint32_t d;
    asm("mapa.shared::cluster.u32 %0, %1, %2;" : "=r"(d) : "r"(a), "r"(rank));
    return d;
}
__device__ __forceinline__ void st_async_remote(uint32_t raddr, float v, uint32_t rmbar) {
    asm volatile("st.async.shared::cluster.mbarrier::complete_tx::bytes.b32 [%0], %1, [%2];"
                 :: "r"(raddr), "r"(__float_as_uint(v)), "r"(rmbar) : "memory");
}
__device__ __forceinline__ void mbar_init(uint32_t mbar, uint32_t cnt) {
    asm volatile("mbarrier.init.shared.b64 [%0], %1;" :: "r"(mbar), "r"(cnt) : "memory");
}
__device__ __forceinline__ void mbar_expect_tx(uint32_t mbar, uint32_t bytes) {
    asm volatile("mbarrier.arrive.expect_tx.shared.b64 _, [%0], %1;" :: "r"(mbar), "r"(bytes) : "memory");
}
__device__ __forceinline__ void mbar_wait(uint32_t mbar, uint32_t parity) {
    uint32_t done;
    asm volatile(
        "{\n\t.reg .pred p;\n\t"
        "mbarrier.try_wait.parity.acquire.cluster.shared::cta.b64 p, [%1], %2;\n\t"
        "selp.b32 %0, 1, 0, p;\n\t}"
        : "=r"(done) : "r"(mbar), "r"(parity) : "memory");
    if (!done) {
        asm volatile(
            "{\n\t.reg .pred P1;\n\t"
            "WL_%=:\n\t"
            "mbarrier.try_wait.parity.acquire.cluster.shared::cta.b64 P1, [%0], %1, 0x989680;\n\t"
            "@P1 bra.uni WD_%=;\n\t"
            "bra.uni WL_%=;\n\t"
            "WD_%=:\n\t}"
            :: "r"(mbar), "r"(parity) : "memory");
    }
}

// ---------------- prep ----------------
__global__ void prep_kernel(const float* __restrict__ Wih0, const float* __restrict__ ffw,
                            const float* __restrict__ ffb,  const float* __restrict__ b0) {
    int g = blockIdx.x * 64 + threadIdx.x;   // 8 * 64
    float v = 0.f, u = 0.f;
    #pragma unroll 8
    for (int k = 0; k < Hd; k++) {
        float w = Wih0[g * Hd + k];
        v = fmaf(w, ffw[k], v);
        u = fmaf(w, ffb[k], u);
    }
    g_v0[g] = v;
    g_u0[g] = u + b0[g];
}

// ---------------- cluster-split LSTM layer (64 clusters of 2 CTAs) ----------------
// Thread owns ONE gate g = rank*256 + tid; 128 W_hh weights packed f32x2 in regs.
// FFMA2 matvec (256-cyc issue floor). NO extra work in the recurrence loop
// (R5/R6/R7 showed any in-loop GEMV costs more than the standalone GEMM).
template <int LAYER>
__global__ __launch_bounds__(256, 1) __cluster_dims__(2, 1, 1)
void lstm_kernel(const float* __restrict__ Whh,
                 const float* __restrict__ xin,
                 const int*   __restrict__ lengths) {
    __shared__ float act[2][G4];
    __shared__ __align__(16) float h_s[Hd];
    __shared__ float xrow[Tlen];
    __shared__ __align__(8) unsigned long long mbar[2];

    const int tid  = threadIdx.x;
    const int rank = blockIdx.x & 1;
    const int b    = blockIdx.x >> 1;
    const int g    = rank * 256 + tid;

    // ---- recurrent weights: 32 x ulonglong2 = 64 packed f32x2 pairs ----
    ulonglong2 w2[32];
    #pragma unroll
    for (int j = 0; j < 32; j++)
        w2[j] = *(const ulonglong2*)(Whh + (size_t)g * Hd + 4 * j);

    uint32_t mb0 = smem_u32(&mbar[0]);
    uint32_t mb1 = smem_u32(&mbar[1]);
    if (tid == 0) {
        mbar_init(mb0, 1); mbar_init(mb1, 1);
        mbar_expect_tx(mb0, 1024); mbar_expect_tx(mb1, 1024);
    }
    const uint32_t peer = rank ^ 1;
    const uint32_t r_act0 = mapa32(smem_u32(&act[0][g]), peer);
    const uint32_t r_act1 = mapa32(smem_u32(&act[1][g]), peer);
    const uint32_t r_mb0  = mapa32(mb0, peer);
    const uint32_t r_mb1  = mapa32(mb1, peer);

    float vg = 0.f, ug = 0.f;
    if (LAYER == 0) {
        vg = g_v0[g]; ug = g_u0[g];
        for (int i = tid; i < Tlen; i += 256) xrow[i] = xin[(size_t)b * Tlen + i];
    }
    if (tid < Hd) h_s[tid] = 0.f;
    __syncthreads();
    asm volatile("barrier.cluster.arrive.aligned;" ::: "memory");
    asm volatile("barrier.cluster.wait.aligned;" ::: "memory");

    float cst = 0.f, sum = 0.f, mx = -INFINITY, last = 0.f;
    const int len = lengths[b];
    uint32_t ph0 = 0, ph1 = 0;

    float zn = 0.f;
    if (LAYER == 1) zn = g_G1[(size_t)b * G4 + g];   // prefetch t=0

    const ulonglong2* h2v = (const ulonglong2*)h_s;

    for (int t = 0; t < Tlen; t++) {
        const int p = t & 1;

        float a_in;
        if (LAYER == 0) {
            a_in = fmaf(xrow[t], vg, ug);
        } else {
            a_in = zn;
            if (t + 1 < Tlen) zn = g_G1[((size_t)(t + 1) * Bsz + b) * G4 + g];
        }
        unsigned long long acc0 = 0ULL, acc1 = 0ULL;
        #pragma unroll
        for (int j = 0; j < 32; j++) {
            ulonglong2 hv = h2v[j];
            fma2(acc0, hv.x, w2[j].x);
            fma2(acc1, hv.y, w2[j].y);
        }
        float2 u0 = upk2(acc0), u1 = upk2(acc1);
        float A = a_in + ((u0.x + u0.y) + (u1.x + u1.y));

        float av;
        if (rank == 0)           av = sigf(A);       // i, f
        else if (tid < 128)      av = tanhfast(A);   // g
        else                     av = sigf(A);       // o

        st_async_remote(p ? r_act1 : r_act0, av, p ? r_mb1 : r_mb0);
        act[p][g] = av;
        __syncthreads();   // local act half visible

        if (tid < Hd) {
            if (p == 0) { mbar_wait(mb0, ph0); } else { mbar_wait(mb1, ph1); }
            if (tid == 0) mbar_expect_tx(p ? mb1 : mb0, 1024);
            float iv = act[p][tid],          fv = act[p][Hd + tid];
            float gv = act[p][2 * Hd + tid], ov = act[p][3 * Hd + tid];
            cst = fmaf(fv, cst, iv * gv);
            float h = ov * tanhfast(cst);
            h_s[tid] = h;
            if (LAYER == 0) {
                if (rank == 0) g_H1[((size_t)t * Bsz + b) * Hd + tid] = h;
            } else if (rank == 0) {
                if (t < len) { sum += h; mx = fmaxf(mx, h); }
                if (t == len - 1) last = h;
            }
        }
        if (p == 0) ph0 ^= 1; else ph1 ^= 1;
        __syncthreads();
    }

    if (LAYER == 1 && rank == 0 && tid < Hd) {
        g_pool[b * 384 + tid]          = sum / (float)len;
        g_pool[b * 384 + Hd + tid]     = mx;
        g_pool[b * 384 + 2 * Hd + tid] = last;
    }
    asm volatile("barrier.cluster.arrive.aligned;" ::: "memory");
    asm volatile("barrier.cluster.wait.aligned;" ::: "memory");
}

// ---------------- GEMM on FFMA2: G1 = H1 @ Wih1^T + b1 (M=131072, N=512, K=128) ----
__global__ __launch_bounds__(256)
void gemm_g1_kernel(const float* __restrict__ Wih1, const float* __restrict__ b1) {
    __shared__ float As[16][128];
    __shared__ float Bs[16][128];
    const int m0 = blockIdx.x * 128;
    const int n0 = blockIdx.y * 128;
    const int tid = threadIdx.x;
    const int tr = (tid >> 4) * 8;
    const int tc = (tid & 15) * 8;

    unsigned long long acc2[8][4];   // [i][j-pair]: (acc[i][2j], acc[i][2j+1])
    #pragma unroll
    for (int i = 0; i < 8; i++)
        #pragma unroll
        for (int j = 0; j < 4; j++) acc2[i][j] = 0ULL;

    for (int k0 = 0; k0 < 128; k0 += 16) {
        for (int l = tid; l < 512; l += 256) {
            int row = l >> 2, c4 = (l & 3) * 4;
            float4 v = *(const float4*)(g_H1 + (size_t)(m0 + row) * 128 + k0 + c4);
            As[c4 + 0][row] = v.x; As[c4 + 1][row] = v.y;
            As[c4 + 2][row] = v.z; As[c4 + 3][row] = v.w;
        }
        for (int l = tid; l < 512; l += 256) {
            int row = l >> 2, c4 = (l & 3) * 4;
            float4 v = *(const float4*)(Wih1 + (size_t)(n0 + row) * 128 + k0 + c4);
            Bs[c4 + 0][row] = v.x; Bs[c4 + 1][row] = v.y;
            Bs[c4 + 2][row] = v.z; Bs[c4 + 3][row] = v.w;
        }
        __syncthreads();
        #pragma unroll
        for (int kk = 0; kk < 16; kk++) {
            float4 a0 = *(const float4*)&As[kk][tr];
            float4 a1 = *(const float4*)&As[kk][tr + 4];
            ulonglong2 bp0 = *(const ulonglong2*)&Bs[kk][tc];       // packed (b0,b1),(b2,b3)
            ulonglong2 bp1 = *(const ulonglong2*)&Bs[kk][tc + 4];   // packed (b4,b5),(b6,b7)
            float ra[8] = {a0.x, a0.y, a0.z, a0.w, a1.x, a1.y, a1.z, a1.w};
            #pragma unroll
            for (int i = 0; i < 8; i++) {
                unsigned long long as = splat2(ra[i]);
                fma2(acc2[i][0], as, bp0.x);
                fma2(acc2[i][1], as, bp0.y);
                fma2(acc2[i][2], as, bp1.x);
                fma2(acc2[i][3], as, bp1.y);
            }
        }
        __syncthreads();
    }
    #pragma unroll
    for (int i = 0; i < 8; i++) {
        #pragma unroll
        for (int j = 0; j < 2; j++) {
            float2 p0 = upk2(acc2[i][2 * j]);
            float2 p1 = upk2(acc2[i][2 * j + 1]);
            float4 v;
            v.x = p0.x + b1[n0 + tc + 4 * j + 0];
            v.y = p0.y + b1[n0 + tc + 4 * j + 1];
            v.z = p1.x + b1[n0 + tc + 4 * j + 2];
            v.w = p1.y + b1[n0 + tc + 4 * j + 3];
            *(float4*)(g_G1 + (size_t)(m0 + tr + i) * G4 + n0 + tc + 4 * j) = v;
        }
    }
}

// ---------------- final linear: 64 CTAs, warp w -> class w ----------------
__global__ __launch_bounds__(256)
void final_kernel(const float* __restrict__ lw, const float* __restrict__ lb,
                  float* __restrict__ out) {
    const int b = blockIdx.x;
    const int wid = threadIdx.x >> 5;
    const int lane = threadIdx.x & 31;
    if (wid >= Cout) return;
    float s = 0.f;
    const float* p = g_pool + b * 384;
    const float* wv = lw + wid * 384;
    #pragma unroll
    for (int j = lane; j < 384; j += 32) s = fmaf(p[j], wv[j], s);
    #pragma unroll
    for (int o = 16; o > 0; o >>= 1) s += __shfl_xor_sync(0xffffffff, s, o);
    if (lane == 0) out[b * Cout + wid] = s + lb[wid];
}

// ---------------- launch ----------------
extern "C" void kernel_launch(void* const* d_in, const int* in_sizes, int n_in,
                              void* d_out, int out_size) {
    const float* x    = (const float*)d_in[0];
    const int*   lens = (const int*)  d_in[1];
    const float* ffw  = (const float*)d_in[2];
    const float* ffb  = (const float*)d_in[3];
    const float* Wih0 = (const float*)d_in[4];
    const float* Whh0 = (const float*)d_in[5];
    const float* b0   = (const float*)d_in[6];
    const float* Wih1 = (const float*)d_in[7];
    const float* Whh1 = (const float*)d_in[8];
    const float* b1   = (const float*)d_in[9];
    const float* lw   = (const float*)d_in[10];
    const float* lb   = (const float*)d_in[11];
    float* out = (float*)d_out;

    prep_kernel<<<8, 64>>>(Wih0, ffw, ffb, b0);
    lstm_kernel<0><<<2 * Bsz, 256>>>(Whh0, x, lens);
    dim3 ggrid((Tlen * Bsz) / 128, G4 / 128);
    gemm_g1_kernel<<<ggrid, 256>>>(Wih1, b1);
    lstm_kernel<1><<<2 * Bsz, 256>>>(Whh1, x, lens);
    final_kernel<<<Bsz, 256>>>(lw, lb, out);
}

// round 9
// speedup vs baseline: 1.4044x; 1.0307x over previous
#include <cuda_runtime.h>
#include <math.h>
#include <stdint.h>

#define Bsz  64
#define Tlen 2048
#define Hd   128
#define G4   512
#define Cout 7

// ---------------- device scratch ----------------
__device__ float g_v0[G4];
__device__ float g_u0[G4];
__device__ float g_H1[(size_t)Tlen * Bsz * Hd];     // layer-0 h stream [t][b][h]
__device__ float g_G1[(size_t)Tlen * Bsz * G4];     // layer-1 input-gate preacts [t][b][g]
__device__ float g_pool[Bsz * 3 * Hd];

__device__ __forceinline__ float sigf(float x)  { return 1.0f / (1.0f + __expf(-x)); }
__device__ __forceinline__ float tanhfast(float x) {
    return fmaf(-2.0f, 1.0f / (__expf(2.0f * x) + 1.0f), 1.0f);
}

// ---- packed f32x2 (Blackwell FFMA2) ----
__device__ __forceinline__ void fma2(unsigned long long& d, unsigned long long a, unsigned long long b) {
    asm("fma.rn.f32x2 %0, %1, %2, %0;" : "+l"(d) : "l"(a), "l"(b));
}
__device__ __forceinline__ float2 upk2(unsigned long long v) {
    float2 r; asm("mov.b64 {%0, %1}, %2;" : "=f"(r.x), "=f"(r.y) : "l"(v)); return r;
}
__device__ __forceinline__ unsigned long long splat2(float f) {
    unsigned long long v; asm("mov.b64 %0, {%1, %1};" : "=l"(v) : "f"(f)); return v;
}

__device__ __forceinline__ uint32_t smem_u32(const void* p) {
    uint32_t a;
    asm("{ .reg .u64 t; cvta.to.shared.u64 t, %1; cvt.u32.u64 %0, t; }" : "=r"(a) : "l"(p));
    return a;
}
__device__ __forceinline__ uint32_t mapa32(uint32_t a, uint32_t rank) {
    uint32_t d;
    asm("mapa.shared::cluster.u32 %0, %1, %2;" : "=r"(d) : "r"(a), "r"(rank));
    return d;
}
__device__ __forceinline__ void st_async_remote(uint32_t raddr, float v, uint32_t rmbar) {
    asm volatile("st.async.shared::cluster.mbarrier::complete_tx::bytes.b32 [%0], %1, [%2];"
                 :: "r"(raddr), "r"(__float_as_uint(v)), "r"(rmbar) : "memory");
}
__device__ __forceinline__ void mbar_init(uint32_t mbar, uint32_t cnt) {
    asm volatile("mbarrier.init.shared.b64 [%0], %1;" :: "r"(mbar), "r"(cnt) : "memory");
}
__device__ __forceinline__ void mbar_expect_tx(uint32_t mbar, uint32_t bytes) {
    asm volatile("mbarrier.arrive.expect_tx.shared.b64 _, [%0], %1;" :: "r"(mbar), "r"(bytes) : "memory");
}
__device__ __forceinline__ void mbar_wait(uint32_t mbar, uint32_t parity) {
    uint32_t done;
    asm volatile(
        "{\n\t.reg .pred p;\n\t"
        "mbarrier.try_wait.parity.acquire.cluster.shared::cta.b64 p, [%1], %2;\n\t"
        "selp.b32 %0, 1, 0, p;\n\t}"
        : "=r"(done) : "r"(mbar), "r"(parity) : "memory");
    if (!done) {
        asm volatile(
            "{\n\t.reg .pred P1;\n\t"
            "WL_%=:\n\t"
            "mbarrier.try_wait.parity.acquire.cluster.shared::cta.b64 P1, [%0], %1, 0x989680;\n\t"
            "@P1 bra.uni WD_%=;\n\t"
            "bra.uni WL_%=;\n\t"
            "WD_%=:\n\t}"
            :: "r"(mbar), "r"(parity) : "memory");
    }
}

// ---------------- prep ----------------
__global__ void prep_kernel(const float* __restrict__ Wih0, const float* __restrict__ ffw,
                            const float* __restrict__ ffb,  const float* __restrict__ b0) {
    int g = blockIdx.x * 64 + threadIdx.x;   // 8 * 64
    float v = 0.f, u = 0.f;
    #pragma unroll 8
    for (int k = 0; k < Hd; k++) {
        float w = Wih0[g * Hd + k];
        v = fmaf(w, ffw[k], v);
        u = fmaf(w, ffb[k], u);
    }
    g_v0[g] = v;
    g_u0[g] = u + b0[g];
}

// ---------------- h-split cluster LSTM (64 clusters of 2 CTAs) ----------------
// Rank r owns ALL FOUR gate types for h-indices [64r, 64r+64): no act exchange.
// Per step only the 64 fresh h values cross CTAs (st.async, 256 B).
// Matvec splits k: local h-half first (hides the DSMEM flight), wait, remote half.
template <int LAYER>
__global__ __launch_bounds__(256, 1) __cluster_dims__(2, 1, 1)
void lstm_kernel(const float* __restrict__ Whh,
                 const float* __restrict__ xin,
                 const int*   __restrict__ lengths) {
    __shared__ __align__(16) float h_s[2][Hd];     // parity double-buffered h
    __shared__ float act_s[256];
    __shared__ float xrow[Tlen];
    __shared__ __align__(8) unsigned long long mbar[2];

    const int tid  = threadIdx.x;
    const int rank = blockIdx.x & 1;
    const int b    = blockIdx.x >> 1;
    const int type = tid >> 6;                     // 0=i 1=f 2=g 3=o
    const int hloc = tid & 63;
    const int h_idx = 64 * rank + hloc;
    const int g    = type * 128 + h_idx;           // global gate index (PyTorch order)
    const int kloc = 64 * rank;                    // local h half (k range)
    const int krem = 64 * (1 - rank);

    // ---- weights reordered at load: w2[0..16) = local k-half, w2[16..32) = remote ----
    ulonglong2 w2[32];
    #pragma unroll
    for (int q = 0; q < 16; q++)
        w2[q] = *(const ulonglong2*)(Whh + (size_t)g * Hd + kloc + 4 * q);
    #pragma unroll
    for (int q = 0; q < 16; q++)
        w2[16 + q] = *(const ulonglong2*)(Whh + (size_t)g * Hd + krem + 4 * q);

    uint32_t mb0 = smem_u32(&mbar[0]);
    uint32_t mb1 = smem_u32(&mbar[1]);
    if (tid == 0) {
        mbar_init(mb0, 1); mbar_init(mb1, 1);
        mbar_expect_tx(mb0, 256); mbar_expect_tx(mb1, 256);   // 64 floats per step
    }
    const uint32_t peer = rank ^ 1;
    // peer h_s[pn][h_idx] (our h_idx lands in peer's REMOTE half)
    const uint32_t r_h0  = mapa32(smem_u32(&h_s[0][h_idx]), peer);
    const uint32_t r_h1  = mapa32(smem_u32(&h_s[1][h_idx]), peer);
    const uint32_t r_mb0 = mapa32(mb0, peer);
    const uint32_t r_mb1 = mapa32(mb1, peer);

    float vg = 0.f, ug = 0.f;
    if (LAYER == 0) {
        vg = g_v0[g]; ug = g_u0[g];
        for (int i = tid; i < Tlen; i += 256) xrow[i] = xin[(size_t)b * Tlen + i];
    }
    if (tid < Hd) h_s[0][tid] = 0.f;
    __syncthreads();
    asm volatile("barrier.cluster.arrive.aligned;" ::: "memory");
    asm volatile("barrier.cluster.wait.aligned;" ::: "memory");

    float cst = 0.f, sum = 0.f, mx = -INFINITY, last = 0.f;
    const int len = lengths[b];
    uint32_t ph0 = 0, ph1 = 0;

    float zn = 0.f;
    if (LAYER == 1) zn = g_G1[(size_t)b * G4 + g];   // prefetch t=0

    for (int t = 0; t < Tlen; t++) {
        const int p  = t & 1;
        const int pn = p ^ 1;

        float a_in;
        if (LAYER == 0) {
            a_in = fmaf(xrow[t], vg, ug);
        } else {
            a_in = zn;
            if (t + 1 < Tlen) zn = g_G1[((size_t)(t + 1) * Bsz + b) * G4 + g];
        }

        const ulonglong2* hp = (const ulonglong2*)h_s[p];
        const ulonglong2* hL = hp + (kloc >> 2);
        const ulonglong2* hR = hp + (krem >> 2);

        // ---- local k-half: starts immediately (peer h still in flight) ----
        unsigned long long acc0 = 0ULL, acc1 = 0ULL;
        #pragma unroll
        for (int q = 0; q < 16; q++) {
            ulonglong2 hv = hL[q];
            fma2(acc0, hv.x, w2[q].x);
            fma2(acc1, hv.y, w2[q].y);
        }
        // ---- wait for peer's 64 h values, then remote k-half ----
        if (t > 0) {
            if (p == 0) { mbar_wait(mb0, ph0); ph0 ^= 1; }
            else        { mbar_wait(mb1, ph1); ph1 ^= 1; }
            if (tid == 0) mbar_expect_tx(p ? mb1 : mb0, 256);   // re-arm for t+2
        }
        #pragma unroll
        for (int q = 0; q < 16; q++) {
            ulonglong2 hv = hR[q];
            fma2(acc0, hv.x, w2[16 + q].x);
            fma2(acc1, hv.y, w2[16 + q].y);
        }
        float2 u0 = upk2(acc0), u1 = upk2(acc1);
        float A = a_in + ((u0.x + u0.y) + (u1.x + u1.y));

        // i,f,o sigmoid; g tanh  (warp-uniform: 64-thread type blocks)
        float av = (type == 2) ? tanhfast(A) : sigf(A);
        act_s[tid] = av;
        __syncthreads();

        if (tid < 64) {
            float iv = act_s[tid],       fv = act_s[64 + tid];
            float gv = act_s[128 + tid], ov = act_s[192 + tid];
            cst = fmaf(fv, cst, iv * gv);
            float h = ov * tanhfast(cst);
            st_async_remote(pn ? r_h1 : r_h0, h, pn ? r_mb1 : r_mb0);  // launch flight first
            h_s[pn][h_idx] = h;
            if (LAYER == 0) {
                g_H1[((size_t)t * Bsz + b) * Hd + h_idx] = h;
            } else {
                if (t < len) { sum += h; mx = fmaxf(mx, h); }
                if (t == len - 1) last = h;
            }
        }
        __syncthreads();
    }

    if (LAYER == 1 && tid < 64) {
        g_pool[b * 384 + h_idx]            = sum / (float)len;
        g_pool[b * 384 + Hd + h_idx]       = mx;
        g_pool[b * 384 + 2 * Hd + h_idx]   = last;
    }
    asm volatile("barrier.cluster.arrive.aligned;" ::: "memory");
    asm volatile("barrier.cluster.wait.aligned;" ::: "memory");
}

// ---------------- GEMM on FFMA2: G1 = H1 @ Wih1^T + b1 (M=131072, N=512, K=128) ----
__global__ __launch_bounds__(256)
void gemm_g1_kernel(const float* __restrict__ Wih1, const float* __restrict__ b1) {
    __shared__ float As[16][128];
    __shared__ float Bs[16][128];
    const int m0 = blockIdx.x * 128;
    const int n0 = blockIdx.y * 128;
    const int tid = threadIdx.x;
    const int tr = (tid >> 4) * 8;
    const int tc = (tid & 15) * 8;

    unsigned long long acc2[8][4];
    #pragma unroll
    for (int i = 0; i < 8; i++)
        #pragma unroll
        for (int j = 0; j < 4; j++) acc2[i][j] = 0ULL;

    for (int k0 = 0; k0 < 128; k0 += 16) {
        for (int l = tid; l < 512; l += 256) {
            int row = l >> 2, c4 = (l & 3) * 4;
            float4 v = *(const float4*)(g_H1 + (size_t)(m0 + row) * 128 + k0 + c4);
            As[c4 + 0][row] = v.x; As[c4 + 1][row] = v.y;
            As[c4 + 2][row] = v.z; As[c4 + 3][row] = v.w;
        }
        for (int l = tid; l < 512; l += 256) {
            int row = l >> 2, c4 = (l & 3) * 4;
            float4 v = *(const float4*)(Wih1 + (size_t)(n0 + row) * 128 + k0 + c4);
            Bs[c4 + 0][row] = v.x; Bs[c4 + 1][row] = v.y;
            Bs[c4 + 2][row] = v.z; Bs[c4 + 3][row] = v.w;
        }
        __syncthreads();
        #pragma unroll
        for (int kk = 0; kk < 16; kk++) {
            float4 a0 = *(const float4*)&As[kk][tr];
            float4 a1 = *(const float4*)&As[kk][tr + 4];
            ulonglong2 bp0 = *(const ulonglong2*)&Bs[kk][tc];
            ulonglong2 bp1 = *(const ulonglong2*)&Bs[kk][tc + 4];
            float ra[8] = {a0.x, a0.y, a0.z, a0.w, a1.x, a1.y, a1.z, a1.w};
            #pragma unroll
            for (int i = 0; i < 8; i++) {
                unsigned long long as = splat2(ra[i]);
                fma2(acc2[i][0], as, bp0.x);
                fma2(acc2[i][1], as, bp0.y);
                fma2(acc2[i][2], as, bp1.x);
                fma2(acc2[i][3], as, bp1.y);
            }
        }
        __syncthreads();
    }
    #pragma unroll
    for (int i = 0; i < 8; i++) {
        #pragma unroll
        for (int j = 0; j < 2; j++) {
            float2 p0 = upk2(acc2[i][2 * j]);
            float2 p1 = upk2(acc2[i][2 * j + 1]);
            float4 v;
            v.x = p0.x + b1[n0 + tc + 4 * j + 0];
            v.y = p0.y + b1[n0 + tc + 4 * j + 1];
            v.z = p1.x + b1[n0 + tc + 4 * j + 2];
            v.w = p1.y + b1[n0 + tc + 4 * j + 3];
            *(float4*)(g_G1 + (size_t)(m0 + tr + i) * G4 + n0 + tc + 4 * j) = v;
        }
    }
}

// ---------------- final linear: 64 CTAs, warp w -> class w ----------------
__global__ __launch_bounds__(256)
void final_kernel(const float* __restrict__ lw, const float* __restrict__ lb,
                  float* __restrict__ out) {
    const int b = blockIdx.x;
    const int wid = threadIdx.x >> 5;
    const int lane = threadIdx.x & 31;
    if (wid >= Cout) return;
    float s = 0.f;
    const float* p = g_pool + b * 384;
    const float* wv = lw + wid * 384;
    #pragma unroll
    for (int j = lane; j < 384; j += 32) s = fmaf(p[j], wv[j], s);
    #pragma unroll
    for (int o = 16; o > 0; o >>= 1) s += __shfl_xor_sync(0xffffffff, s, o);
    if (lane == 0) out[b * Cout + wid] = s + lb[wid];
}

// ---------------- launch ----------------
extern "C" void kernel_launch(void* const* d_in, const int* in_sizes, int n_in,
                              void* d_out, int out_size) {
    const float* x    = (const float*)d_in[0];
    const int*   lens = (const int*)  d_in[1];
    const float* ffw  = (const float*)d_in[2];
    const float* ffb  = (const float*)d_in[3];
    const float* Wih0 = (const float*)d_in[4];
    const float* Whh0 = (const float*)d_in[5];
    const float* b0   = (const float*)d_in[6];
    const float* Wih1 = (const float*)d_in[7];
    const float* Whh1 = (const float*)d_in[8];
    const float* b1   = (const float*)d_in[9];
    const float* lw   = (const float*)d_in[10];
    const float* lb   = (const float*)d_in[11];
    float* out = (float*)d_out;

    prep_kernel<<<8, 64>>>(Wih0, ffw, ffb, b0);
    lstm_kernel<0><<<2 * Bsz, 256>>>(Whh0, x, lens);
    dim3 ggrid((Tlen * Bsz) / 128, G4 / 128);
    gemm_g1_kernel<<<ggrid, 256>>>(Wih1, b1);
    lstm_kernel<1><<<2 * Bsz, 256>>>(Whh1, x, lens);
    final_kernel<<<Bsz, 256>>>(lw, lb, out);
}